// round 7
// baseline (speedup 1.0000x reference)
#include <cuda_runtime.h>
#include <cstdint>
#include <math.h>

// NeuralField fused: hashgrid encode + 3-layer MLP on mma.sync TF32 + final dot.
// CTA = 128 points, 512 threads (16 warps): warp tile 32x64
// (4 M-quarters x 4 N-quarters), acc[2][8][4]. Same SMEM/traffic as R6 but
// 4 warps/SMSP for latency hiding.

#define NLEV    8
#define NPTS    262144
#define THREADS 512

#define HA_PITCH 72           // 72 % 32 == 8 -> conflict-free LDS.64
#define HB_PITCH 264          // 264 % 32 == 8

#define B1_OFF   0                           // 128 x 264 activations (+ encode alias)
#define BS_OFF   (128 * HB_PITCH)            // 33792
#define BS_F     8192                        // fragment-major chunk: 32KB
#define W3_OFF   (BS_OFF + 2 * BS_F)         // 50176
#define SMEM_FLOATS (W3_OFF + 256)
#define SMEM_BYTES  (SMEM_FLOATS * 4)        // 201728

#define NCHUNK 18  // layer0: g 0..1 (K=64), layer1: 2..9, layer2: 10..17

struct LevelParams { float scale[NLEV]; int res[NLEV]; int size[NLEV]; };

// fragment-major weights: [18][nq(4)][kk(4)][j(4)][lane(32)][e(4)]
__device__ float g_Wf[18 * BS_F];

// ------------------------------- helpers -----------------------------------
__device__ __forceinline__ uint32_t smem_u32(const void* p) {
    uint32_t a;
    asm("{ .reg .u64 t; cvta.to.shared.u64 t, %1; cvt.u32.u64 %0, t; }"
        : "=r"(a) : "l"(p));
    return a;
}
__device__ __forceinline__ uint32_t tf32r(float f) {
    uint32_t u;
    asm("cvt.rna.tf32.f32 %0, %1;" : "=r"(u) : "f"(f));
    return u;
}
__device__ __forceinline__ void cp_async16(uint32_t dst, const void* src) {
    asm volatile("cp.async.cg.shared.global [%0], [%1], 16;" :: "r"(dst), "l"(src));
}
#define CP_COMMIT() asm volatile("cp.async.commit_group;" ::: "memory")
#define CP_WAIT0()  asm volatile("cp.async.wait_group 0;" ::: "memory")

__device__ __forceinline__ void mma_tf32(float* d, const uint32_t* a,
                                         uint32_t b0, uint32_t b1) {
    asm volatile(
        "mma.sync.aligned.m16n8k8.row.col.f32.tf32.tf32.f32 "
        "{%0,%1,%2,%3}, {%4,%5,%6,%7}, {%8,%9}, {%0,%1,%2,%3};"
        : "+f"(d[0]), "+f"(d[1]), "+f"(d[2]), "+f"(d[3])
        : "r"(a[0]), "r"(a[1]), "r"(a[2]), "r"(a[3]), "r"(b0), "r"(b1));
}

// ---------------- prep: gather weights into fragment order + tf32 -----------
__global__ void wt_prep(const float* __restrict__ W0,
                        const float* __restrict__ W1,
                        const float* __restrict__ W2)
{
    const int idx = blockIdx.x * 256 + threadIdx.x;    // 0 .. 147455
    const int g    = idx >> 13;
    const int r    = idx & 8191;
    const int nq   = r >> 11;
    const int kkI  = (r >> 9) & 3;
    const int j    = (r >> 7) & 3;
    const int lane = (r >> 2) & 31;
    const int e    = r & 3;
    const int grp  = lane >> 2, tig = lane & 3;
    const int i16  = j * 4 + e;
    const int nt   = i16 >> 1;
    const int b    = i16 & 1;

    const float* W; int kc;
    if (g < 2)       { W = W0; kc = g * 32; }
    else if (g < 10) { W = W1; kc = (g - 2) * 32; }
    else             { W = W2; kc = (g - 10) * 32; }

    const int k = kc + kkI * 8 + 2 * tig + b;          // k-permuted slot
    const int n = nq * 64 + nt * 8 + grp;
    g_Wf[idx] = __uint_as_float(tf32r(W[k * 256 + n]));
}

// --------------------------------- main kernel ------------------------------
__device__ __forceinline__ void prefetch_chunk(int g, uint32_t bs_base, int tid)
{
    const float* src = g_Wf + g * BS_F;
    const uint32_t dst = bs_base + (uint32_t)(g & 1) * (BS_F * 4);
    #pragma unroll
    for (int it = 0; it < 4; ++it) {
        const int i = tid + it * 512;                  // 0..2047 float4s, contiguous
        cp_async16(dst + (uint32_t)i * 16, src + i * 4);
    }
    CP_COMMIT();
}

__global__ __launch_bounds__(THREADS, 1)
void nf_main(const float* __restrict__ x, const float* __restrict__ table,
             const float* __restrict__ W3, float* __restrict__ out, LevelParams lp)
{
    extern __shared__ float smem[];
    float* B1  = smem + B1_OFF;
    float* W3s = smem + W3_OFF;
    const uint32_t bs_base = smem_u32(smem + BS_OFF);

    const int tid  = threadIdx.x;
    const int wid  = tid >> 5;
    const int lane = tid & 31;
    const int grp  = lane >> 2;
    const int tig  = lane & 3;
    const int mb   = (wid & 3) * 32;     // M-quarter base row
    const int nq   = wid >> 2;           // N-quarter
    const int nb   = nq * 64;

    prefetch_chunk(0, bs_base, tid);     // overlaps encode

    if (tid < 256) W3s[tid] = W3[tid];

    // ---------------- Encode: 4 threads/point, 2 levels/thread --------------
    {
        const int p    = tid & 127;
        const int quad = tid >> 7;           // 0..3 -> levels {2q, 2q+1}
        const int gp   = blockIdx.x * 128 + p;
        const float xx = x[2 * gp];
        const float yy = x[2 * gp + 1];

        #pragma unroll
        for (int li = 0; li < 2; ++li) {
            const int l     = quad * 2 + li;
            const float s   = lp.scale[l];
            const int res   = lp.res[l];
            const int size  = lp.size[l];

            const float posx = xx * s + 0.5f;
            const float posy = yy * s + 0.5f;
            const float gx = floorf(posx), gy = floorf(posy);
            const float fx = posx - gx,    fy = posy - gy;
            const int   ix = (int)gx,      iy = (int)gy;
            const float wx = fx * fx * (3.0f - 2.0f * fx);
            const float wy = fy * fy * (3.0f - 2.0f * fy);

            float f[8];
            #pragma unroll
            for (int j = 0; j < 8; ++j) f[j] = 0.0f;

            #pragma unroll
            for (int dx = 0; dx < 2; ++dx) {
                const float wxx = dx ? wx : (1.0f - wx);
                #pragma unroll
                for (int dy = 0; dy < 2; ++dy) {
                    const float wyy = dy ? wy : (1.0f - wy);
                    const int idx = ((ix + dx) + (iy + dy) * res) % size;
                    const float4* tp =
                        (const float4*)(table + ((size_t)(l * 8192 + idx) << 3));
                    const float w = wxx * wyy;
                    const float4 t0 = tp[0];
                    const float4 t1 = tp[1];
                    f[0] += w * t0.x; f[1] += w * t0.y;
                    f[2] += w * t0.z; f[3] += w * t0.w;
                    f[4] += w * t1.x; f[5] += w * t1.y;
                    f[6] += w * t1.z; f[7] += w * t1.w;
                }
            }
            float4 v0, v1;
            v0.x = __uint_as_float(tf32r(f[0])); v0.y = __uint_as_float(tf32r(f[1]));
            v0.z = __uint_as_float(tf32r(f[2])); v0.w = __uint_as_float(tf32r(f[3]));
            v1.x = __uint_as_float(tf32r(f[4])); v1.y = __uint_as_float(tf32r(f[5]));
            v1.z = __uint_as_float(tf32r(f[6])); v1.w = __uint_as_float(tf32r(f[7]));
            *(float4*)&B1[p * HA_PITCH + l * 8]     = v0;
            *(float4*)&B1[p * HA_PITCH + l * 8 + 4] = v1;
        }
    }

    // ---------------- 18 chunks across 3 layers ------------------------------
    float acc[2][8][4];
    #pragma unroll
    for (int mt = 0; mt < 2; ++mt)
        #pragma unroll
        for (int nt = 0; nt < 8; ++nt)
            #pragma unroll
            for (int q = 0; q < 4; ++q) acc[mt][nt][q] = 0.0f;

    for (int g = 0; g < NCHUNK; ++g) {
        CP_WAIT0();
        __syncthreads();
        if (g + 1 < NCHUNK) prefetch_chunk(g + 1, bs_base, tid);

        const int layer = (g < 2) ? 0 : ((g < 10) ? 1 : 2);
        const int kc0   = 32 * ((layer == 0) ? g : ((layer == 1) ? g - 2 : g - 10));
        const int ap    = (layer == 0) ? HA_PITCH : HB_PITCH;
        const float* Bs = smem + BS_OFF + (g & 1) * BS_F;

        #pragma unroll
        for (int kkI = 0; kkI < 4; ++kkI) {
            // A fragments: LDS.64 pairs (phys cols 2tig, 2tig+1)
            const int acol = kc0 + kkI * 8 + 2 * tig;
            uint32_t a[2][4];
            #pragma unroll
            for (int mt = 0; mt < 2; ++mt) {
                const int r0 = (mb + mt * 16 + grp) * ap + acol;
                const float2 p0 = *(const float2*)&B1[r0];
                const float2 p1 = *(const float2*)&B1[r0 + 8 * ap];
                a[mt][0] = __float_as_uint(p0.x);
                a[mt][1] = __float_as_uint(p1.x);
                a[mt][2] = __float_as_uint(p0.y);
                a[mt][3] = __float_as_uint(p1.y);
            }
            // B fragments: 4x LDS.128, fragment-major, conflict-free
            float bf[16];
            #pragma unroll
            for (int j = 0; j < 4; ++j)
                *(float4*)&bf[j * 4] =
                    *(const float4*)&Bs[((nq * 4 + kkI) * 4 + j) * 128 + lane * 4];

            #pragma unroll
            for (int nt = 0; nt < 8; ++nt) {
                const uint32_t b0 = __float_as_uint(bf[nt * 2]);
                const uint32_t b1 = __float_as_uint(bf[nt * 2 + 1]);
                #pragma unroll
                for (int mt = 0; mt < 2; ++mt)
                    mma_tf32(acc[mt][nt], a[mt], b0, b1);
            }
        }

        if (g == 1 || g == 9 || g == 17) {
            __syncthreads();        // all reads of B1 done -> in-place write OK
            const bool last = (g == 17);
            #pragma unroll
            for (int mt = 0; mt < 2; ++mt)
                #pragma unroll
                for (int nt = 0; nt < 8; ++nt) {
                    const int r0 = mb + mt * 16 + grp;
                    const int c0 = nb + nt * 8 + tig * 2;
                    float v0 = fmaxf(acc[mt][nt][0], 0.0f);
                    float v1 = fmaxf(acc[mt][nt][1], 0.0f);
                    float v2 = fmaxf(acc[mt][nt][2], 0.0f);
                    float v3 = fmaxf(acc[mt][nt][3], 0.0f);
                    if (!last) {
                        v0 = __uint_as_float(tf32r(v0));
                        v1 = __uint_as_float(tf32r(v1));
                        v2 = __uint_as_float(tf32r(v2));
                        v3 = __uint_as_float(tf32r(v3));
                    }
                    float2 w01; w01.x = v0; w01.y = v1;
                    float2 w23; w23.x = v2; w23.y = v3;
                    *(float2*)&B1[r0 * HB_PITCH + c0]       = w01;
                    *(float2*)&B1[(r0 + 8) * HB_PITCH + c0] = w23;
                    acc[mt][nt][0] = 0.0f; acc[mt][nt][1] = 0.0f;
                    acc[mt][nt][2] = 0.0f; acc[mt][nt][3] = 0.0f;
                }
        }
    }
    __syncthreads();

    // ---------------- Final: relu(h3) . W3, 4 threads/row --------------------
    {
        const int row = tid >> 2;
        const int seg = tid & 3;
        const float* h = B1 + row * HB_PITCH + seg * 64;
        const float* w = W3s + seg * 64;
        float s = 0.0f;
        #pragma unroll 16
        for (int k = 0; k < 64; ++k)
            s = fmaf(h[k], w[k], s);
        s += __shfl_xor_sync(0xffffffffu, s, 1);
        s += __shfl_xor_sync(0xffffffffu, s, 2);
        if (seg == 0) out[blockIdx.x * 128 + row] = s;
    }
}

// --------------------------------- launcher ---------------------------------
extern "C" void kernel_launch(void* const* d_in, const int* in_sizes, int n_in,
                              void* d_out, int out_size)
{
    const float* x     = (const float*)d_in[0];
    const float* table = (const float*)d_in[1];
    const float* W0    = (const float*)d_in[2];
    const float* W1    = (const float*)d_in[3];
    const float* W2    = (const float*)d_in[4];
    const float* W3    = (const float*)d_in[5];
    float*       out   = (float*)d_out;

    LevelParams lp;
    for (int l = 0; l < NLEV; ++l) {
        double sc = 16.0 * pow(1.2599210739135742, (double)l) - 1.0;
        int res = (int)ceil(sc) + 1;
        long long sz = (long long)res * (long long)res;
        sz = ((sz + 7) / 8) * 8;
        if (sz > (1LL << 19)) sz = 1LL << 19;
        lp.scale[l] = (float)sc;
        lp.res[l]   = res;
        lp.size[l]  = (int)sz;
    }

    wt_prep<<<576, 256>>>(W0, W1, W2);

    cudaFuncSetAttribute(nf_main, cudaFuncAttributeMaxDynamicSharedMemorySize,
                         SMEM_BYTES);
    nf_main<<<NPTS / 128, THREADS, SMEM_BYTES>>>(x, table, W3, out, lp);
}

// round 8
// speedup vs baseline: 1.1448x; 1.1448x over previous
#include <cuda_runtime.h>
#include <cstdint>
#include <math.h>

// NeuralField fused: hashgrid encode + 3-layer MLP on mma.sync TF32 + final dot.
// CTA = 128 points, 256 threads (8 warps), warp tile 64x64. Fragment-native
// SMEM layouts (R6) + register double-buffered fragment pipeline (this round):
// kkI+1's A/B fragments are loaded before kkI's 32 mmas issue, so LDS latency
// hides under tensor work.

#define NLEV    8
#define NPTS    262144
#define THREADS 256

#define HA_PITCH 72           // 72 % 32 == 8 -> conflict-free LDS.64
#define HB_PITCH 264          // 264 % 32 == 8

#define B1_OFF   0                           // 128 x 264 activations (+ encode alias)
#define BS_OFF   (128 * HB_PITCH)            // 33792
#define BS_F     8192                        // fragment-major chunk: 32KB
#define W3_OFF   (BS_OFF + 2 * BS_F)         // 50176
#define SMEM_FLOATS (W3_OFF + 256)
#define SMEM_BYTES  (SMEM_FLOATS * 4)        // 201728

#define NCHUNK 18  // layer0: g 0..1 (K=64), layer1: 2..9, layer2: 10..17

struct LevelParams { float scale[NLEV]; int res[NLEV]; int size[NLEV]; };

// fragment-major weights: [18][nq(4)][kk(4)][j(4)][lane(32)][e(4)]
__device__ float g_Wf[18 * BS_F];

// ------------------------------- helpers -----------------------------------
__device__ __forceinline__ uint32_t smem_u32(const void* p) {
    uint32_t a;
    asm("{ .reg .u64 t; cvta.to.shared.u64 t, %1; cvt.u32.u64 %0, t; }"
        : "=r"(a) : "l"(p));
    return a;
}
__device__ __forceinline__ uint32_t tf32r(float f) {
    uint32_t u;
    asm("cvt.rna.tf32.f32 %0, %1;" : "=r"(u) : "f"(f));
    return u;
}
__device__ __forceinline__ void cp_async16(uint32_t dst, const void* src) {
    asm volatile("cp.async.cg.shared.global [%0], [%1], 16;" :: "r"(dst), "l"(src));
}
#define CP_COMMIT() asm volatile("cp.async.commit_group;" ::: "memory")
#define CP_WAIT0()  asm volatile("cp.async.wait_group 0;" ::: "memory")

__device__ __forceinline__ void mma_tf32(float* d, const uint32_t* a,
                                         uint32_t b0, uint32_t b1) {
    asm volatile(
        "mma.sync.aligned.m16n8k8.row.col.f32.tf32.tf32.f32 "
        "{%0,%1,%2,%3}, {%4,%5,%6,%7}, {%8,%9}, {%0,%1,%2,%3};"
        : "+f"(d[0]), "+f"(d[1]), "+f"(d[2]), "+f"(d[3])
        : "r"(a[0]), "r"(a[1]), "r"(a[2]), "r"(a[3]), "r"(b0), "r"(b1));
}

// ---------------- prep: gather weights into fragment order + tf32 -----------
__global__ void wt_prep(const float* __restrict__ W0,
                        const float* __restrict__ W1,
                        const float* __restrict__ W2)
{
    const int idx = blockIdx.x * 256 + threadIdx.x;    // 0 .. 147455
    const int g    = idx >> 13;
    const int r    = idx & 8191;
    const int nq   = r >> 11;
    const int kkI  = (r >> 9) & 3;
    const int j    = (r >> 7) & 3;
    const int lane = (r >> 2) & 31;
    const int e    = r & 3;
    const int grp  = lane >> 2, tig = lane & 3;
    const int i16  = j * 4 + e;
    const int nt   = i16 >> 1;
    const int b    = i16 & 1;

    const float* W; int kc;
    if (g < 2)       { W = W0; kc = g * 32; }
    else if (g < 10) { W = W1; kc = (g - 2) * 32; }
    else             { W = W2; kc = (g - 10) * 32; }

    const int k = kc + kkI * 8 + 2 * tig + b;          // k-permuted slot
    const int n = nq * 64 + nt * 8 + grp;
    g_Wf[idx] = __uint_as_float(tf32r(W[k * 256 + n]));
}

// --------------------------------- main kernel ------------------------------
__device__ __forceinline__ void prefetch_chunk(int g, uint32_t bs_base, int tid)
{
    const float* src = g_Wf + g * BS_F;
    const uint32_t dst = bs_base + (uint32_t)(g & 1) * (BS_F * 4);
    #pragma unroll
    for (int it = 0; it < 8; ++it) {
        const int i = tid + it * 256;                  // 0..2047 float4s, contiguous
        cp_async16(dst + (uint32_t)i * 16, src + i * 4);
    }
    CP_COMMIT();
}

__global__ __launch_bounds__(THREADS, 1)
void nf_main(const float* __restrict__ x, const float* __restrict__ table,
             const float* __restrict__ W3, float* __restrict__ out, LevelParams lp)
{
    extern __shared__ float smem[];
    float* B1  = smem + B1_OFF;
    float* W3s = smem + W3_OFF;
    const uint32_t bs_base = smem_u32(smem + BS_OFF);

    const int tid  = threadIdx.x;
    const int wid  = tid >> 5;
    const int lane = tid & 31;
    const int grp  = lane >> 2;
    const int tig  = lane & 3;
    const int mb   = (wid & 1) * 64;
    const int nq   = wid >> 1;
    const int nb   = nq * 64;

    prefetch_chunk(0, bs_base, tid);     // overlaps encode

    W3s[tid] = W3[tid];

    // ---------------- Encode: 2 threads/point, 4 levels/thread --------------
    {
        const int p    = tid & 127;
        const int half = tid >> 7;
        const int gp   = blockIdx.x * 128 + p;
        const float xx = x[2 * gp];
        const float yy = x[2 * gp + 1];

        #pragma unroll
        for (int li = 0; li < 4; ++li) {
            const int l     = half * 4 + li;
            const float s   = lp.scale[l];
            const int res   = lp.res[l];
            const int size  = lp.size[l];

            const float posx = xx * s + 0.5f;
            const float posy = yy * s + 0.5f;
            const float gx = floorf(posx), gy = floorf(posy);
            const float fx = posx - gx,    fy = posy - gy;
            const int   ix = (int)gx,      iy = (int)gy;
            const float wx = fx * fx * (3.0f - 2.0f * fx);
            const float wy = fy * fy * (3.0f - 2.0f * fy);

            float f[8];
            #pragma unroll
            for (int j = 0; j < 8; ++j) f[j] = 0.0f;

            #pragma unroll
            for (int dx = 0; dx < 2; ++dx) {
                const float wxx = dx ? wx : (1.0f - wx);
                #pragma unroll
                for (int dy = 0; dy < 2; ++dy) {
                    const float wyy = dy ? wy : (1.0f - wy);
                    const int idx = ((ix + dx) + (iy + dy) * res) % size;
                    const float4* tp =
                        (const float4*)(table + ((size_t)(l * 8192 + idx) << 3));
                    const float w = wxx * wyy;
                    const float4 t0 = tp[0];
                    const float4 t1 = tp[1];
                    f[0] += w * t0.x; f[1] += w * t0.y;
                    f[2] += w * t0.z; f[3] += w * t0.w;
                    f[4] += w * t1.x; f[5] += w * t1.y;
                    f[6] += w * t1.z; f[7] += w * t1.w;
                }
            }
            float4 v0, v1;
            v0.x = __uint_as_float(tf32r(f[0])); v0.y = __uint_as_float(tf32r(f[1]));
            v0.z = __uint_as_float(tf32r(f[2])); v0.w = __uint_as_float(tf32r(f[3]));
            v1.x = __uint_as_float(tf32r(f[4])); v1.y = __uint_as_float(tf32r(f[5]));
            v1.z = __uint_as_float(tf32r(f[6])); v1.w = __uint_as_float(tf32r(f[7]));
            *(float4*)&B1[p * HA_PITCH + l * 8]     = v0;
            *(float4*)&B1[p * HA_PITCH + l * 8 + 4] = v1;
        }
    }

    // ---------------- 18 chunks across 3 layers ------------------------------
    float acc[4][8][4];
    #pragma unroll
    for (int mt = 0; mt < 4; ++mt)
        #pragma unroll
        for (int nt = 0; nt < 8; ++nt)
            #pragma unroll
            for (int q = 0; q < 4; ++q) acc[mt][nt][q] = 0.0f;

    // register-pipelined fragment buffers
    uint32_t a[2][4][4];
    float    bf[2][16];

#define LOADFRAG(kk, slot) do {                                                   \
    const int _acol = kc0 + (kk) * 8 + 2 * tig;                                   \
    _Pragma("unroll")                                                             \
    for (int mt = 0; mt < 4; ++mt) {                                              \
        const int _r0 = (mb + mt * 16 + grp) * ap + _acol;                        \
        const float2 _p0 = *(const float2*)&B1[_r0];                              \
        const float2 _p1 = *(const float2*)&B1[_r0 + 8 * ap];                     \
        a[slot][mt][0] = __float_as_uint(_p0.x);                                  \
        a[slot][mt][1] = __float_as_uint(_p1.x);                                  \
        a[slot][mt][2] = __float_as_uint(_p0.y);                                  \
        a[slot][mt][3] = __float_as_uint(_p1.y);                                  \
    }                                                                             \
    _Pragma("unroll")                                                             \
    for (int j = 0; j < 4; ++j)                                                   \
        *(float4*)&bf[slot][j * 4] =                                              \
            *(const float4*)&Bs[((nq * 4 + (kk)) * 4 + j) * 128 + lane * 4];      \
} while (0)

    for (int g = 0; g < NCHUNK; ++g) {
        CP_WAIT0();
        __syncthreads();
        if (g + 1 < NCHUNK) prefetch_chunk(g + 1, bs_base, tid);

        const int layer = (g < 2) ? 0 : ((g < 10) ? 1 : 2);
        const int kc0   = 32 * ((layer == 0) ? g : ((layer == 1) ? g - 2 : g - 10));
        const int ap    = (layer == 0) ? HA_PITCH : HB_PITCH;
        const float* Bs = smem + BS_OFF + (g & 1) * BS_F;

        LOADFRAG(0, 0);
        #pragma unroll
        for (int kkI = 0; kkI < 4; ++kkI) {
            const int cur = kkI & 1;
            if (kkI < 3) LOADFRAG(kkI + 1, cur ^ 1);   // hide LDS under mmas below
            #pragma unroll
            for (int nt = 0; nt < 8; ++nt) {
                const uint32_t b0 = __float_as_uint(bf[cur][nt * 2]);
                const uint32_t b1 = __float_as_uint(bf[cur][nt * 2 + 1]);
                #pragma unroll
                for (int mt = 0; mt < 4; ++mt)
                    mma_tf32(acc[mt][nt], a[cur][mt], b0, b1);
            }
        }

        if (g == 1 || g == 9 || g == 17) {
            __syncthreads();        // all reads of B1 done -> in-place write OK
            const bool last = (g == 17);
            #pragma unroll
            for (int mt = 0; mt < 4; ++mt)
                #pragma unroll
                for (int nt = 0; nt < 8; ++nt) {
                    const int r0 = mb + mt * 16 + grp;
                    const int c0 = nb + nt * 8 + tig * 2;
                    float v0 = fmaxf(acc[mt][nt][0], 0.0f);
                    float v1 = fmaxf(acc[mt][nt][1], 0.0f);
                    float v2 = fmaxf(acc[mt][nt][2], 0.0f);
                    float v3 = fmaxf(acc[mt][nt][3], 0.0f);
                    if (!last) {
                        v0 = __uint_as_float(tf32r(v0));
                        v1 = __uint_as_float(tf32r(v1));
                        v2 = __uint_as_float(tf32r(v2));
                        v3 = __uint_as_float(tf32r(v3));
                    }
                    float2 w01; w01.x = v0; w01.y = v1;
                    float2 w23; w23.x = v2; w23.y = v3;
                    *(float2*)&B1[r0 * HB_PITCH + c0]       = w01;
                    *(float2*)&B1[(r0 + 8) * HB_PITCH + c0] = w23;
                    acc[mt][nt][0] = 0.0f; acc[mt][nt][1] = 0.0f;
                    acc[mt][nt][2] = 0.0f; acc[mt][nt][3] = 0.0f;
                }
        }
    }
    __syncthreads();

    // ---------------- Final: relu(h3) . W3, 2 threads/row --------------------
    {
        const int row = tid >> 1;
        const int seg = tid & 1;
        const float* h = B1 + row * HB_PITCH + seg * 128;
        const float* w = W3s + seg * 128;
        float s = 0.0f;
        #pragma unroll 16
        for (int k = 0; k < 128; ++k)
            s = fmaf(h[k], w[k], s);
        s += __shfl_xor_sync(0xffffffffu, s, 1);
        if (seg == 0) out[blockIdx.x * 128 + row] = s;
    }
}

// --------------------------------- launcher ---------------------------------
extern "C" void kernel_launch(void* const* d_in, const int* in_sizes, int n_in,
                              void* d_out, int out_size)
{
    const float* x     = (const float*)d_in[0];
    const float* table = (const float*)d_in[1];
    const float* W0    = (const float*)d_in[2];
    const float* W1    = (const float*)d_in[3];
    const float* W2    = (const float*)d_in[4];
    const float* W3    = (const float*)d_in[5];
    float*       out   = (float*)d_out;

    LevelParams lp;
    for (int l = 0; l < NLEV; ++l) {
        double sc = 16.0 * pow(1.2599210739135742, (double)l) - 1.0;
        int res = (int)ceil(sc) + 1;
        long long sz = (long long)res * (long long)res;
        sz = ((sz + 7) / 8) * 8;
        if (sz > (1LL << 19)) sz = 1LL << 19;
        lp.scale[l] = (float)sc;
        lp.res[l]   = res;
        lp.size[l]  = (int)sz;
    }

    wt_prep<<<576, 256>>>(W0, W1, W2);

    cudaFuncSetAttribute(nf_main, cudaFuncAttributeMaxDynamicSharedMemorySize,
                         SMEM_BYTES);
    nf_main<<<NPTS / 128, THREADS, SMEM_BYTES>>>(x, table, W3, out, lp);
}